// round 4
// baseline (speedup 1.0000x reference)
#include <cuda_runtime.h>
#include <math.h>

#define HH 512
#define WW 512
#define BB 16
#define NPIX (HH*WW)
#define NTOT (BB*NPIX)

#define F_A 0.955f
#define F_B 1.3693f
#define F_INF 1e6f

// Scratch (device globals; no allocation allowed)
__device__ float  g_d[NTOT];          // distance grid / code grid
__device__ float  g_maxd[BB];         // per-sample max of final DT
__device__ int    g_hasfg[BB];
__device__ int    g_hasb[BB];
__device__ double g_acc[2 + 3*BB];    // [0]=focal sum, [1]=bnd sum, [2..]=inter, psum, tsum per sample

// ---------------------------------------------------------------------------
__global__ void zero_kernel() {
    int t = threadIdx.x;
    if (t < 2 + 3*BB) g_acc[t] = 0.0;
    if (t < BB) { g_hasfg[t] = 0; g_hasb[t] = 0; }
}

// ---------------------------------------------------------------------------
// Per-pixel: m = (target!=0); boundary = (exists in-bounds nb with m==1) &&
// (exists in-bounds nb with m==0). Encodes code = boundary*2 + m into g_d,
// and OR-reduces per-sample has_fg / has_boundary flags.
__global__ void __launch_bounds__(256) flags_kernel(const int* __restrict__ tgt) {
    int b = blockIdx.y;
    const int* T = tgt + b * NPIX;
    float* D = g_d + b * NPIX;
    int fg = 0, bd = 0;
    int start = blockIdx.x * 8192;
    for (int i = start + threadIdx.x; i < start + 8192; i += 256) {
        int y = i >> 9, x = i & 511;
        int any1 = 0, any0 = 0;
        #pragma unroll
        for (int dy = -1; dy <= 1; dy++) {
            int yy = y + dy;
            if ((unsigned)yy >= (unsigned)HH) continue;
            #pragma unroll
            for (int dx = -1; dx <= 1; dx++) {
                int xx = x + dx;
                if ((unsigned)xx >= (unsigned)WW) continue;
                int v = T[yy * WW + xx];
                any1 |= (v != 0);
                any0 |= (v == 0);
            }
        }
        int m = (T[i] != 0);
        int bound = any1 & any0;
        fg |= m; bd |= bound;
        D[i] = (float)((bound << 1) | m);
    }
    fg = __syncthreads_or(fg);
    bd = __syncthreads_or(bd);
    if (threadIdx.x == 0) {
        if (fg) atomicOr(&g_hasfg[b], 1);
        if (bd) atomicOr(&g_hasb[b], 1);
    }
}

// ---------------------------------------------------------------------------
// seeds = has_b ? boundary : (m < 0.5);  d = seed ? 0 : INF
__global__ void __launch_bounds__(256) seed_kernel() {
    int b = blockIdx.y;
    int hb = g_hasb[b];
    float* D = g_d + b * NPIX;
    int start = blockIdx.x * 4096;
    for (int i = start + threadIdx.x; i < start + 4096; i += 256) {
        int code = (int)D[i];
        int seed = hb ? (code >> 1) : ((code & 1) ^ 1);
        D[i] = seed ? 0.0f : F_INF;
    }
}

// ---------------------------------------------------------------------------
// One raster chamfer pass. REV=false: top-left -> bottom-right (logical ==
// physical). REV=true: operate on the both-axes-flipped grid (logical row r =
// physical row H-1-r, logical col j = physical col W-1-j), which reproduces
// pass(d[::-1,::-1])[::-1,::-1]. Bitwise-identical fp32 ops vs the reference
// (min is exact; additions/multiplies in the same order).
template<bool REV, bool DOMAX>
__global__ void __launch_bounds__(512, 1) chamfer_kernel() {
    int b = blockIdx.x;
    float* img = g_d + b * NPIX;
    const int j = threadIdx.x;
    const int lane = j & 31;
    const int wid = j >> 5;
    __shared__ float shp[WW + 2];   // previous logical row, padded
    __shared__ float shw[16];       // warp scan totals

    shp[j + 1] = F_INF;
    if (j == 0) { shp[0] = F_INF; shp[WW + 1] = F_INF; }

    const int pc = REV ? (WW - 1 - j) : j;
    const float aj = F_A * (float)j;

    int pr0 = REV ? (HH - 1) : 0;
    float nxt = img[pr0 * WW + pc];
    float runmax = 0.0f;
    __syncthreads();

    for (int r = 0; r < HH; r++) {
        float drow = nxt;
        int pr = REV ? (HH - 1 - r) : r;
        if (r + 1 < HH) {
            int prn = REV ? (HH - 2 - r) : (r + 1);
            nxt = img[prn * WW + pc];
        }
        float up = shp[j + 1] + F_A;
        float ul = shp[j]     + F_B;
        float ur = shp[j + 2] + F_B;
        float m = fminf(fminf(drow, up), fminf(ul, ur));
        float v = m - aj;
        // warp inclusive min-scan
        #pragma unroll
        for (int o = 1; o < 32; o <<= 1) {
            float n = __shfl_up_sync(0xffffffffu, v, o);
            if (lane >= o) v = fminf(v, n);
        }
        if (lane == 31) shw[wid] = v;
        __syncthreads();
        // cross-warp exclusive prefix (wid uniform per warp -> uniform loop)
        float pre = 3.4e38f;
        for (int w = 0; w < wid; w++) pre = fminf(pre, shw[w]);
        if (wid > 0) v = fminf(v, pre);
        float cur = aj + v;
        shp[j + 1] = cur;              // safe: all shp reads done before sync above
        img[pr * WW + pc] = cur;
        if (DOMAX) runmax = fmaxf(runmax, cur);
        __syncthreads();
    }

    if (DOMAX) {
        #pragma unroll
        for (int o = 16; o > 0; o >>= 1)
            runmax = fmaxf(runmax, __shfl_xor_sync(0xffffffffu, runmax, o));
        if (lane == 0) shw[wid] = runmax;
        __syncthreads();
        if (j == 0) {
            float mx = shw[0];
            #pragma unroll
            for (int w = 1; w < 16; w++) mx = fmaxf(mx, shw[w]);
            g_maxd[b] = mx;
        }
    }
}

// ---------------------------------------------------------------------------
// Fused loss: focal, boundary (with normalized dist), per-sample sums for
// dice/iou. Block partials -> double atomics.
__global__ void __launch_bounds__(256) loss_kernel(const float* __restrict__ pred,
                                                   const int* __restrict__ tgt) {
    int b = blockIdx.y;
    int base = b * NPIX + blockIdx.x * 4096;
    float mx = g_maxd[b];
    float scale = (mx > 0.0f) ? (1.0f / fmaxf(mx, 1e-12f)) : 1.0f;
    int hasfg = g_hasfg[b];

    float a_f = 0.0f, a_b = 0.0f, a_i = 0.0f, a_p = 0.0f, a_t = 0.0f;
    #pragma unroll 4
    for (int k = 0; k < 16; k++) {
        int gi = base + threadIdx.x + k * 256;
        float x = pred[gi];
        float t = (tgt[gi] != 0) ? 1.0f : 0.0f;
        float e = expf(-fabsf(x));
        float l1p = log1pf(e);
        float s = 1.0f / (1.0f + e);
        float p = (x >= 0.0f) ? s : 1.0f - s;          // sigmoid(x)
        float ls_x  = fminf(x, 0.0f)  - l1p;           // log sigmoid(x)
        float ls_nx = fminf(-x, 0.0f) - l1p;           // log sigmoid(-x)
        float bce = -(t * ls_x + (1.0f - t) * ls_nx);
        float pt = t * p + (1.0f - t) * (1.0f - p);
        float at = (t == 1.0f) ? 0.25f : 0.75f;
        float om = 1.0f - pt;
        a_f += at * om * om * bce;
        float dn = hasfg ? (g_d[gi] * scale) : 1.0f;
        a_b += (t * (1.0f - p) + (1.0f - t) * p) * (1.0f + dn);
        a_i += p * t;
        a_p += p;
        a_t += t;
    }

    // block reduce (8 warps)
    #pragma unroll
    for (int o = 16; o > 0; o >>= 1) {
        a_f += __shfl_down_sync(0xffffffffu, a_f, o);
        a_b += __shfl_down_sync(0xffffffffu, a_b, o);
        a_i += __shfl_down_sync(0xffffffffu, a_i, o);
        a_p += __shfl_down_sync(0xffffffffu, a_p, o);
        a_t += __shfl_down_sync(0xffffffffu, a_t, o);
    }
    __shared__ float red[8][5];
    int lane = threadIdx.x & 31, wid = threadIdx.x >> 5;
    if (lane == 0) {
        red[wid][0] = a_f; red[wid][1] = a_b; red[wid][2] = a_i;
        red[wid][3] = a_p; red[wid][4] = a_t;
    }
    __syncthreads();
    if (threadIdx.x == 0) {
        float s0 = 0, s1 = 0, s2 = 0, s3 = 0, s4 = 0;
        #pragma unroll
        for (int w = 0; w < 8; w++) {
            s0 += red[w][0]; s1 += red[w][1]; s2 += red[w][2];
            s3 += red[w][3]; s4 += red[w][4];
        }
        atomicAdd(&g_acc[0], (double)s0);
        atomicAdd(&g_acc[1], (double)s1);
        atomicAdd(&g_acc[2 + b], (double)s2);
        atomicAdd(&g_acc[2 + BB + b], (double)s3);
        atomicAdd(&g_acc[2 + 2*BB + b], (double)s4);
    }
}

// ---------------------------------------------------------------------------
__global__ void finalize_kernel(const float* __restrict__ lv, float* __restrict__ out) {
    if (threadIdx.x == 0) {
        double N = (double)NTOT;
        double focal = g_acc[0] / N;
        double bnd   = g_acc[1] / N;
        double dsum = 0.0, isum = 0.0;
        for (int b = 0; b < BB; b++) {
            double inter = g_acc[2 + b];
            double ps = g_acc[2 + BB + b];
            double ts = g_acc[2 + 2*BB + b];
            double tot = ps + ts;
            dsum += (2.0 * inter + 1e-6) / (tot + 1e-6);
            isum += (inter + 1e-6) / (tot - inter + 1e-6);
        }
        double dice = 1.0 - dsum / (double)BB;
        double iou  = 1.0 - isum / (double)BB;
        float f = (float)focal, d = (float)dice, bb = (float)bnd, io = (float)iou;
        float total = expf(-lv[0]) * f + lv[0]
                    + expf(-lv[1]) * d + lv[1]
                    + expf(-lv[2]) * bb + lv[2]
                    + expf(-lv[3]) * io + lv[3];
        out[0] = total;
        out[1] = f;
        out[2] = d;
        out[3] = bb;
        out[4] = io;
    }
}

// ---------------------------------------------------------------------------
extern "C" void kernel_launch(void* const* d_in, const int* in_sizes, int n_in,
                              void* d_out, int out_size) {
    const float* pred = (const float*)d_in[0];
    const int*   tgt  = (const int*)d_in[1];
    const float* lv   = (const float*)d_in[2];
    float* out = (float*)d_out;

    zero_kernel<<<1, 64>>>();
    flags_kernel<<<dim3(32, BB), 256>>>(tgt);
    seed_kernel<<<dim3(64, BB), 256>>>();
    chamfer_kernel<false, false><<<BB, 512>>>();
    chamfer_kernel<true,  true ><<<BB, 512>>>();
    loss_kernel<<<dim3(64, BB), 256>>>(pred, tgt);
    finalize_kernel<<<1, 32>>>(lv, out);
}